// round 12
// baseline (speedup 1.0000x reference)
#include <cuda_runtime.h>
#include <cuda_bf16.h>
#include <cuda_fp8.h>
#include <cstdint>

// ---------------------------------------------------------------------------
// GCNEncoder, collapsed form.
//   out = (1/n) (sum_j c[j] h1[j]) W2 + b2
//   c[j]  = dis[j] * ( sum_{edges src=j} dis[dst] + dis[j] )
//   h1[i] = relu( dis[i]*(sum_{j in N_in(i)} h'[j] + h'[i]) + b1 )
//   h'[j] = (x W1)[j] * dis[j]   -- stored e4m3; gather is 256B/row (L2-res).
// Layer-1 GEMM: single-term bf16 mma.m16n8k16. GRID = (2, Mtiles): the two
// N-tiles of one M-tile are adjacent bids -> co-resident -> the second one's
// A-tile reads hit L2 instead of DRAM (halves the dominant A stream).
// CSR edge-scatter fused into the GEMM tail.
// ---------------------------------------------------------------------------

#define NMAX 100000
#define EMAX 3200000
#define DIM  256
#define AGG_BLOCKS ((NMAX + 7) / 8)

__device__ int   g_deg[NMAX];
__device__ float g_dis[NMAX];
__device__ float g_coef[NMAX];
__device__ int   g_rowptr[NMAX + 1];
__device__ int   g_cursor[NMAX];
__device__ int   g_col[EMAX];
__device__ __align__(16) uint8_t g_h8[(size_t)NMAX * DIM];  // h' in e4m3
__device__ float g_part[(size_t)AGG_BLOCKS * DIM];
__device__ float g_part2[256 * DIM];
__device__ int   g_bsum[256];

// ---------------------------- degree / CSR build ---------------------------

__global__ void k_count(const int* __restrict__ dst, int e) {
    int i = blockIdx.x * blockDim.x + threadIdx.x;
    if (i < e) atomicAdd(&g_deg[dst[i]], 1);
}

// block TOTALS over 1024-entry chunks; also computes dis = rsqrt(deg+1)
__global__ void k_block_sums(int n) {
    __shared__ int sh[256];
    int base = blockIdx.x * 1024;
    int s = 0;
#pragma unroll
    for (int q = 0; q < 4; q++) {
        int i = base + q * 256 + threadIdx.x;
        if (i < n) {
            int d = g_deg[i];
            s += d;
            g_dis[i] = rsqrtf((float)d + 1.0f);
        }
    }
    sh[threadIdx.x] = s;
    __syncthreads();
    for (int off = 128; off > 0; off >>= 1) {
        if (threadIdx.x < off) sh[threadIdx.x] += sh[threadIdx.x + off];
        __syncthreads();
    }
    if (threadIdx.x == 0) g_bsum[blockIdx.x] = sh[0];
}

// per-block scan; each block derives its global offset from preceding totals
__global__ void k_scan_blocks(int n, int e_total) {
    __shared__ int sh[1024];
    __shared__ int wsum[32];

    int pre = (threadIdx.x < blockIdx.x) ? g_bsum[threadIdx.x] : 0;
#pragma unroll
    for (int off = 16; off > 0; off >>= 1)
        pre += __shfl_down_sync(0xffffffffu, pre, off);
    if ((threadIdx.x & 31) == 0) wsum[threadIdx.x >> 5] = pre;
    __syncthreads();
    if (threadIdx.x == 0) {
        int s = 0;
#pragma unroll
        for (int w = 0; w < 32; w++) s += wsum[w];
        wsum[0] = s;
    }
    __syncthreads();
    int blockoff = wsum[0];

    int i = blockIdx.x * 1024 + threadIdx.x;
    int v = (i < n) ? g_deg[i] : 0;
    sh[threadIdx.x] = v;
    __syncthreads();
    for (int off = 1; off < 1024; off <<= 1) {
        int t = 0;
        if ((int)threadIdx.x >= off) t = sh[threadIdx.x - off];
        __syncthreads();
        sh[threadIdx.x] += t;
        __syncthreads();
    }
    int excl = sh[threadIdx.x] - v;
    if (i < n) {
        int r = excl + blockoff;
        g_rowptr[i] = r;
        g_cursor[i] = r;
    }
    if (i == 0) g_rowptr[n] = e_total;
}

// ---------------- single-term bf16 tensor-core GEMM + scatter ---------------
// Block 128x128; grid (2, Mtiles): x = N-tile, y = M-tile (pair adjacency).
// BK=16, 8 warps (4x2), warp tile 32x64.

#define AS 24
#define BSTR 136

__device__ __forceinline__ uint32_t smem_u32(const void* p) {
    return (uint32_t)__cvta_generic_to_shared(p);
}

__device__ __forceinline__ void ldsm4(uint32_t* r, uint32_t a) {
    asm volatile("ldmatrix.sync.aligned.m8n8.x4.shared.b16 {%0,%1,%2,%3}, [%4];"
                 : "=r"(r[0]), "=r"(r[1]), "=r"(r[2]), "=r"(r[3]) : "r"(a));
}

__device__ __forceinline__ void ldsm4t(uint32_t* r, uint32_t a) {
    asm volatile("ldmatrix.sync.aligned.m8n8.x4.trans.shared.b16 {%0,%1,%2,%3}, [%4];"
                 : "=r"(r[0]), "=r"(r[1]), "=r"(r[2]), "=r"(r[3]) : "r"(a));
}

__device__ __forceinline__ void mma_bf16(float* d, const uint32_t* a, uint32_t b0, uint32_t b1) {
    asm volatile(
        "mma.sync.aligned.m16n8k16.row.col.f32.bf16.bf16.f32 "
        "{%0,%1,%2,%3}, {%4,%5,%6,%7}, {%8,%9}, {%0,%1,%2,%3};"
        : "+f"(d[0]), "+f"(d[1]), "+f"(d[2]), "+f"(d[3])
        : "r"(a[0]), "r"(a[1]), "r"(a[2]), "r"(a[3]), "r"(b0), "r"(b1));
}

// float4 -> two bf16x2 words
__device__ __forceinline__ uint2 pack4(float4 v) {
    __nv_bfloat162 a = __floats2bfloat162_rn(v.x, v.y);
    __nv_bfloat162 b = __floats2bfloat162_rn(v.z, v.w);
    return make_uint2(*(uint32_t*)&a, *(uint32_t*)&b);
}

// pack two f32 into e4m3x2 (result .b16; first PTX src packs the high byte)
__device__ __forceinline__ uint16_t f2e4m3x2(float a, float b) {
    uint16_t r;
    asm("cvt.rn.satfinite.e4m3x2.f32 %0, %1, %2;" : "=h"(r) : "f"(b), "f"(a));
    return r;
}

__global__ __launch_bounds__(256, 2)
void k_gemm_scatter(const float* __restrict__ A, const float* __restrict__ B, int M,
                    const int* __restrict__ esrc, const int* __restrict__ edst, int E) {
    __shared__ __nv_bfloat16 Ah[128 * AS];
    __shared__ __nv_bfloat16 Bh[16 * BSTR];

    int tid = threadIdx.x;
    int bm = blockIdx.y * 128;   // M-tile (grid.y)
    int bn = blockIdx.x * 128;   // N-tile (grid.x = 2; pair-adjacent bids)
    int wid = tid >> 5;
    int lane = tid & 31;
    int wm = (wid & 3) * 32;
    int wn = (wid >> 2) * 64;
    int qr = lane >> 2, qc = lane & 3;

    int ar0 = (tid + 0) >> 2, ac0 = ((tid + 0) & 3) << 2;
    int ar1 = (tid + 256) >> 2, ac1 = ((tid + 256) & 3) << 2;
    int bk0 = (tid + 0) >> 5, bn0 = ((tid + 0) & 31) << 2;
    int bk1 = (tid + 256) >> 5, bn1 = ((tid + 256) & 31) << 2;

    int la = lane & 15, lb = lane >> 4;
    uint32_t adAh = smem_u32(Ah) + (uint32_t)(((wm + la) * AS + lb * 8) * 2);
    uint32_t adBh = smem_u32(Bh) + (uint32_t)((la * BSTR + wn + lb * 8) * 2);

    float d[2][8][4];
#pragma unroll
    for (int i = 0; i < 2; i++)
#pragma unroll
        for (int j = 0; j < 8; j++)
#pragma unroll
            for (int q = 0; q < 4; q++) d[i][j][q] = 0.0f;

    float4 pa0, pa1, pb0, pb1;
    {
        int g0 = bm + ar0, g1 = bm + ar1;
        pa0 = (g0 < M) ? *(const float4*)(A + (size_t)g0 * 256 + ac0) : make_float4(0.f, 0.f, 0.f, 0.f);
        pa1 = (g1 < M) ? *(const float4*)(A + (size_t)g1 * 256 + ac1) : make_float4(0.f, 0.f, 0.f, 0.f);
        pb0 = *(const float4*)(B + (size_t)bk0 * 256 + bn + bn0);
        pb1 = *(const float4*)(B + (size_t)bk1 * 256 + bn + bn1);
    }

    for (int t8 = 0; t8 < 16; t8++) {
        *(uint2*)&Ah[ar0 * AS + ac0] = pack4(pa0);
        *(uint2*)&Ah[ar1 * AS + ac1] = pack4(pa1);
        *(uint2*)&Bh[bk0 * BSTR + bn0] = pack4(pb0);
        *(uint2*)&Bh[bk1 * BSTR + bn1] = pack4(pb1);
        __syncthreads();

        if (t8 < 15) {
            int k0 = (t8 + 1) * 16;
            int g0 = bm + ar0, g1 = bm + ar1;
            pa0 = (g0 < M) ? *(const float4*)(A + (size_t)g0 * 256 + k0 + ac0) : make_float4(0.f, 0.f, 0.f, 0.f);
            pa1 = (g1 < M) ? *(const float4*)(A + (size_t)g1 * 256 + k0 + ac1) : make_float4(0.f, 0.f, 0.f, 0.f);
            pb0 = *(const float4*)(B + (size_t)(k0 + bk0) * 256 + bn + bn0);
            pb1 = *(const float4*)(B + (size_t)(k0 + bk1) * 256 + bn + bn1);
        }

        {
            uint32_t ah0[4], ah1[4];
            ldsm4(ah0, adAh);
            ldsm4(ah1, adAh + 16 * AS * 2);
#pragma unroll
            for (int t = 0; t < 4; t++) {
                uint32_t bh[4];
                ldsm4t(bh, adBh + t * 32);
                mma_bf16(d[0][2 * t],     ah0, bh[0], bh[1]);
                mma_bf16(d[1][2 * t],     ah1, bh[0], bh[1]);
                mma_bf16(d[0][2 * t + 1], ah0, bh[2], bh[3]);
                mma_bf16(d[1][2 * t + 1], ah1, bh[2], bh[3]);
            }
        }
        __syncthreads();
    }

    // epilogue: * dis[row], convert to e4m3 pairs, 2B stores
#pragma unroll
    for (int ma = 0; ma < 2; ma++) {
        int r0 = bm + wm + 16 * ma + qr;
        int r1 = r0 + 8;
        float w0 = (r0 < M) ? g_dis[r0] : 0.0f;
        float w1 = (r1 < M) ? g_dis[r1] : 0.0f;
#pragma unroll
        for (int na = 0; na < 8; na++) {
            int c = bn + wn + 8 * na + 2 * qc;
            if (r0 < M) {
                uint16_t p = f2e4m3x2(d[ma][na][0] * w0, d[ma][na][1] * w0);
                *(uint16_t*)(&g_h8[(size_t)r0 * 256 + c]) = p;
            }
            if (r1 < M) {
                uint16_t p = f2e4m3x2(d[ma][na][2] * w1, d[ma][na][3] * w1);
                *(uint16_t*)(&g_h8[(size_t)r1 * 256 + c]) = p;
            }
        }
    }

    // ---- tail: scatter this block's slice of edges into CSR (+ coef) ----
    {
        int nblocks = gridDim.x * gridDim.y;
        int bid = blockIdx.y * gridDim.x + blockIdx.x;
        int per = (E + nblocks - 1) / nblocks;
        int e0 = bid * per;
        int e1 = min(e0 + per, E);
        for (int i = e0 + tid; i < e1; i += 256) {
            int s = esrc[i];
            int dd = edst[i];
            int p = atomicAdd(&g_cursor[dd], 1);
            g_col[p] = s;
            atomicAdd(&g_coef[s], g_dis[dd]);
        }
    }
}

// -------------------- fused aggregation + weighted reduce -------------------
// 8 rows / block (one warp per row). Lane l owns cols l*8..l*8+7 = one uint2
// of 8 e4m3; unpack cvt.rn.f16x2.e4m3x2, accumulate half2.

__device__ __forceinline__ __half2 e8_to_h2(uint16_t w) {
    uint32_t r;
    asm("cvt.rn.f16x2.e4m3x2 %0, %1;" : "=r"(r) : "h"(w));
    return *(__half2*)&r;
}

__global__ __launch_bounds__(256)
void k_agg_fused(const float* __restrict__ bias, int n) {
    __shared__ float sh[8][256];

    int lane = threadIdx.x & 31;
    int w = threadIdx.x >> 5;
    int i = blockIdx.x * 8 + w;

    const uint2* __restrict__ hp = (const uint2*)g_h8;  // row = 32 uint2
    float res[8];
#pragma unroll
    for (int q = 0; q < 8; q++) res[q] = 0.0f;

    if (i < n) {
        int s = g_rowptr[i];
        int t = g_rowptr[i + 1];
        float di = g_dis[i];
        float ci = di * (g_coef[i] + di);

        __half2 acc[4];
        {
            uint2 sv = hp[(size_t)i * 32 + lane];
            acc[0] = e8_to_h2((uint16_t)(sv.x & 0xffffu));
            acc[1] = e8_to_h2((uint16_t)(sv.x >> 16));
            acc[2] = e8_to_h2((uint16_t)(sv.y & 0xffffu));
            acc[3] = e8_to_h2((uint16_t)(sv.y >> 16));
        }

        for (int base = s; base < t; base += 32) {
            int m = min(32, t - base);
            int jv = (base + lane < t) ? g_col[base + lane] : 0;
#pragma unroll 8
            for (int k = 0; k < m; k++) {
                int j = __shfl_sync(0xffffffffu, jv, k);
                uint2 v = hp[(size_t)j * 32 + lane];
                acc[0] = __hadd2(acc[0], e8_to_h2((uint16_t)(v.x & 0xffffu)));
                acc[1] = __hadd2(acc[1], e8_to_h2((uint16_t)(v.x >> 16)));
                acc[2] = __hadd2(acc[2], e8_to_h2((uint16_t)(v.y & 0xffffu)));
                acc[3] = __hadd2(acc[3], e8_to_h2((uint16_t)(v.y >> 16)));
            }
        }

        float4 b0 = *(const float4*)(bias + lane * 8);
        float4 b1 = *(const float4*)(bias + lane * 8 + 4);
        float2 f0 = __half22float2(acc[0]);
        float2 f1 = __half22float2(acc[1]);
        float2 f2 = __half22float2(acc[2]);
        float2 f3 = __half22float2(acc[3]);
        res[0] = fmaxf(f0.x * di + b0.x, 0.f) * ci;
        res[1] = fmaxf(f0.y * di + b0.y, 0.f) * ci;
        res[2] = fmaxf(f1.x * di + b0.z, 0.f) * ci;
        res[3] = fmaxf(f1.y * di + b0.w, 0.f) * ci;
        res[4] = fmaxf(f2.x * di + b1.x, 0.f) * ci;
        res[5] = fmaxf(f2.y * di + b1.y, 0.f) * ci;
        res[6] = fmaxf(f3.x * di + b1.z, 0.f) * ci;
        res[7] = fmaxf(f3.y * di + b1.w, 0.f) * ci;
    }

#pragma unroll
    for (int q = 0; q < 8; q++) sh[w][lane * 8 + q] = res[q];
    __syncthreads();

    int c = threadIdx.x;
    float ssum = 0.0f;
#pragma unroll
    for (int q = 0; q < 8; q++) ssum += sh[q][c];
    g_part[(size_t)blockIdx.x * 256 + c] = ssum;
}

// ------------------------------- reductions --------------------------------

__global__ void k_reduce_stage1(int nb) {
    int c = threadIdx.x;
    int rows_per = (nb + 255) / 256;
    int r0 = blockIdx.x * rows_per;
    int r1 = min(r0 + rows_per, nb);
    float s = 0.0f;
    for (int r = r0; r < r1; r++) s += g_part[(size_t)r * 256 + c];
    g_part2[blockIdx.x * 256 + c] = s;
}

__global__ void k_final(const float* __restrict__ W2, const float* __restrict__ b2,
                        float* __restrict__ out, int n) {
    __shared__ float z[256];
    int c = threadIdx.x;
    float s = 0.0f;
    for (int b = 0; b < 256; b++) s += g_part2[b * 256 + c];
    z[c] = s / (float)n;
    __syncthreads();

    float o = b2[c];
#pragma unroll 8
    for (int k = 0; k < 256; k++) o += z[k] * W2[k * 256 + c];
    out[c] = o;
}

// -------------------------------- launch -----------------------------------

extern "C" void kernel_launch(void* const* d_in, const int* in_sizes, int n_in,
                              void* d_out, int out_size) {
    const float* x  = (const float*)d_in[0];
    const float* W1 = (const float*)d_in[1];
    const float* b1 = (const float*)d_in[2];
    const float* W2 = (const float*)d_in[3];
    const float* b2 = (const float*)d_in[4];
    const int*   ei = (const int*)d_in[5];

    int n = in_sizes[0] / DIM;
    int e = in_sizes[5] / 2;
    const int* src = ei;
    const int* dst = ei + e;
    float* out = (float*)d_out;

    int nb1024 = (n + 1023) / 1024;
    int agg_blocks = (n + 7) / 8;

    // zero deg/coef via memset nodes (not kernel launches)
    void* p_deg;
    void* p_coef;
    cudaGetSymbolAddress(&p_deg, g_deg);
    cudaGetSymbolAddress(&p_coef, g_coef);
    cudaMemsetAsync(p_deg, 0, (size_t)n * sizeof(int));
    cudaMemsetAsync(p_coef, 0, (size_t)n * sizeof(float));

    // --- degree / dis / rowptr ---
    k_count<<<(e + 255) / 256, 256>>>(dst, e);
    k_block_sums<<<nb1024, 256>>>(n);          // dis + block totals
    k_scan_blocks<<<nb1024, 1024>>>(n, e);     // rowptr + cursor

    // --- layer-1 GEMM (bf16) + fused edge scatter; N-tile pairs adjacent ---
    dim3 gemm_grid(2, (n + 127) / 128);
    k_gemm_scatter<<<gemm_grid, 256>>>(x, W1, n, src, dst, e);

    // --- fused aggregate + relu + weighted reduce (layer 2 collapsed) ---
    k_agg_fused<<<agg_blocks, 256>>>(b1, n);

    // --- reduce partials, matvec with W2, bias, mean ---
    k_reduce_stage1<<<256, 256>>>(agg_blocks);
    k_final<<<1, 256>>>(W2, b2, out, n);
}

// round 13
// speedup vs baseline: 1.0606x; 1.0606x over previous
#include <cuda_runtime.h>
#include <cuda_bf16.h>
#include <cuda_fp8.h>
#include <cstdint>

// ---------------------------------------------------------------------------
// GCNEncoder, collapsed form.
//   out = (1/n) (sum_j c[j] h1[j]) W2 + b2
//   c[j]  = dis[j] * ( sum_{edges src=j} dis[dst] + dis[j] )
//   h1[i] = relu( dis[i]*(sum_{j in N_in(i)} h'[j] + h'[i]) + b1 )
//   h'[j] = (x W1)[j] * dis[j]   -- stored e4m3; gather 256B/row (L2-res).
//
// R12 finding: GEMM was MLP-bound (1 TB/s of 8 available). Fix:
//   - x, W1 pre-converted to bf16 inside k_count (same rounding as before,
//     streams at HBM rate, halves GEMM A traffic)
//   - GEMM consumes bf16 via 4-stage cp.async ring -> deep MLP
// CSR edge-scatter stays fused into the GEMM tail.
// ---------------------------------------------------------------------------

#define NMAX 100000
#define EMAX 3200000
#define DIM  256
#define AGG_BLOCKS ((NMAX + 7) / 8)

__device__ int   g_deg[NMAX];
__device__ float g_dis[NMAX];
__device__ float g_coef[NMAX];
__device__ int   g_rowptr[NMAX + 1];
__device__ int   g_cursor[NMAX];
__device__ int   g_col[EMAX];
__device__ __align__(16) __nv_bfloat16 g_xb[(size_t)NMAX * DIM];  // x in bf16
__device__ __align__(16) __nv_bfloat16 g_wb[DIM * DIM];           // W1 in bf16
__device__ __align__(16) uint8_t g_h8[(size_t)NMAX * DIM];        // h' in e4m3
__device__ float g_part[(size_t)AGG_BLOCKS * DIM];
__device__ float g_part2[256 * DIM];
__device__ int   g_bsum[256];

// ------------------------------- helpers -----------------------------------

__device__ __forceinline__ uint32_t smem_u32(const void* p) {
    return (uint32_t)__cvta_generic_to_shared(p);
}

// float4 -> two bf16x2 words
__device__ __forceinline__ uint2 pack4(float4 v) {
    __nv_bfloat162 a = __floats2bfloat162_rn(v.x, v.y);
    __nv_bfloat162 b = __floats2bfloat162_rn(v.z, v.w);
    return make_uint2(*(uint32_t*)&a, *(uint32_t*)&b);
}

__device__ __forceinline__ void cp_async16(uint32_t smem, const void* g, int src_bytes) {
    asm volatile("cp.async.cg.shared.global [%0], [%1], 16, %2;"
                 :: "r"(smem), "l"(g), "r"(src_bytes) : "memory");
}
__device__ __forceinline__ void cp_commit() {
    asm volatile("cp.async.commit_group;" ::: "memory");
}
template <int N>
__device__ __forceinline__ void cp_wait() {
    asm volatile("cp.async.wait_group %0;" :: "n"(N) : "memory");
}

__device__ __forceinline__ void ldsm4(uint32_t* r, uint32_t a) {
    asm volatile("ldmatrix.sync.aligned.m8n8.x4.shared.b16 {%0,%1,%2,%3}, [%4];"
                 : "=r"(r[0]), "=r"(r[1]), "=r"(r[2]), "=r"(r[3]) : "r"(a));
}
__device__ __forceinline__ void ldsm4t(uint32_t* r, uint32_t a) {
    asm volatile("ldmatrix.sync.aligned.m8n8.x4.trans.shared.b16 {%0,%1,%2,%3}, [%4];"
                 : "=r"(r[0]), "=r"(r[1]), "=r"(r[2]), "=r"(r[3]) : "r"(a));
}
__device__ __forceinline__ void mma_bf16(float* d, const uint32_t* a, uint32_t b0, uint32_t b1) {
    asm volatile(
        "mma.sync.aligned.m16n8k16.row.col.f32.bf16.bf16.f32 "
        "{%0,%1,%2,%3}, {%4,%5,%6,%7}, {%8,%9}, {%0,%1,%2,%3};"
        : "+f"(d[0]), "+f"(d[1]), "+f"(d[2]), "+f"(d[3])
        : "r"(a[0]), "r"(a[1]), "r"(a[2]), "r"(a[3]), "r"(b0), "r"(b1));
}

// pack two f32 into e4m3x2 (result .b16; first PTX src packs the high byte)
__device__ __forceinline__ uint16_t f2e4m3x2(float a, float b) {
    uint16_t r;
    asm("cvt.rn.satfinite.e4m3x2.f32 %0, %1, %2;" : "=h"(r) : "f"(b), "f"(a));
    return r;
}

// ---------------------- degree count + bf16 conversion ---------------------
// 3.2M threads: per-edge degree atomic, plus grid-stride conversion of
// x (100MB->50MB) and W1 to bf16. Streaming hides the atomic latency.

__global__ void k_count_convert(const int* __restrict__ dst, int e,
                                const float* __restrict__ x,
                                const float* __restrict__ W1, int n) {
    int i = blockIdx.x * blockDim.x + threadIdx.x;
    int nth = gridDim.x * blockDim.x;
    if (i < e) atomicAdd(&g_deg[dst[i]], 1);

    const float4* __restrict__ x4 = (const float4*)x;
    uint2* __restrict__ xb2 = (uint2*)g_xb;
    int total4 = n * (DIM / 4);
    for (int idx = i; idx < total4; idx += nth)
        xb2[idx] = pack4(x4[idx]);

    const float4* __restrict__ w4 = (const float4*)W1;
    uint2* __restrict__ wb2 = (uint2*)g_wb;
    for (int idx = i; idx < DIM * DIM / 4; idx += nth)
        wb2[idx] = pack4(w4[idx]);
}

// block TOTALS over 1024-entry chunks; also computes dis = rsqrt(deg+1)
__global__ void k_block_sums(int n) {
    __shared__ int sh[256];
    int base = blockIdx.x * 1024;
    int s = 0;
#pragma unroll
    for (int q = 0; q < 4; q++) {
        int i = base + q * 256 + threadIdx.x;
        if (i < n) {
            int d = g_deg[i];
            s += d;
            g_dis[i] = rsqrtf((float)d + 1.0f);
        }
    }
    sh[threadIdx.x] = s;
    __syncthreads();
    for (int off = 128; off > 0; off >>= 1) {
        if (threadIdx.x < off) sh[threadIdx.x] += sh[threadIdx.x + off];
        __syncthreads();
    }
    if (threadIdx.x == 0) g_bsum[blockIdx.x] = sh[0];
}

// per-block scan; each block derives its global offset from preceding totals
__global__ void k_scan_blocks(int n, int e_total) {
    __shared__ int sh[1024];
    __shared__ int wsum[32];

    int pre = (threadIdx.x < blockIdx.x) ? g_bsum[threadIdx.x] : 0;
#pragma unroll
    for (int off = 16; off > 0; off >>= 1)
        pre += __shfl_down_sync(0xffffffffu, pre, off);
    if ((threadIdx.x & 31) == 0) wsum[threadIdx.x >> 5] = pre;
    __syncthreads();
    if (threadIdx.x == 0) {
        int s = 0;
#pragma unroll
        for (int w = 0; w < 32; w++) s += wsum[w];
        wsum[0] = s;
    }
    __syncthreads();
    int blockoff = wsum[0];

    int i = blockIdx.x * 1024 + threadIdx.x;
    int v = (i < n) ? g_deg[i] : 0;
    sh[threadIdx.x] = v;
    __syncthreads();
    for (int off = 1; off < 1024; off <<= 1) {
        int t = 0;
        if ((int)threadIdx.x >= off) t = sh[threadIdx.x - off];
        __syncthreads();
        sh[threadIdx.x] += t;
        __syncthreads();
    }
    int excl = sh[threadIdx.x] - v;
    if (i < n) {
        int r = excl + blockoff;
        g_rowptr[i] = r;
        g_cursor[i] = r;
    }
    if (i == 0) g_rowptr[n] = e_total;
}

// ------------- bf16 GEMM, 4-stage cp.async pipeline, + scatter --------------
// Block 128x128; grid (2, Mtiles) keeps the N-tile pair co-resident for L2
// A-reuse. BK=16, 8 warps (4x2), warp tile 32x64.

#define AS 24
#define BSTR 136
#define STAGES 4
#define A_TILE (128 * AS)
#define B_TILE (16 * BSTR)

__global__ __launch_bounds__(256, 2)
void k_gemm_scatter(int M, const int* __restrict__ esrc,
                    const int* __restrict__ edst, int E) {
    __shared__ __nv_bfloat16 Ah[STAGES * A_TILE];
    __shared__ __nv_bfloat16 Bh[STAGES * B_TILE];

    int tid = threadIdx.x;
    int bm = blockIdx.y * 128;   // M-tile
    int bn = blockIdx.x * 128;   // N-tile (grid.x = 2)
    int wid = tid >> 5;
    int lane = tid & 31;
    int wm = (wid & 3) * 32;
    int wn = (wid >> 2) * 64;
    int qr = lane >> 2, qc = lane & 3;

    // cp.async chunk mapping: A tile 128 rows x 2 chunks; B tile 16 rows x 16
    int arow = tid >> 1, ach = (tid & 1) * 8;       // elems
    int brow = tid >> 4, bch = (tid & 15) * 8;      // elems
    const __nv_bfloat16* Ag = g_xb;
    const __nv_bfloat16* Bg = g_wb;
    uint32_t adA = smem_u32(&Ah[arow * AS + ach]);
    uint32_t adB = smem_u32(&Bh[brow * BSTR + bch]);
    int aValid = (bm + arow < M) ? 16 : 0;
    const __nv_bfloat16* aSrcBase = Ag + (size_t)(bm + arow) * 256 + ach;
    const __nv_bfloat16* bSrcBase = Bg + (size_t)brow * 256 + bn + bch;

    // ldmatrix lane addresses (within stage 0)
    int la = lane & 15, lb = lane >> 4;
    uint32_t adAh = smem_u32(Ah) + (uint32_t)(((wm + la) * AS + lb * 8) * 2);
    uint32_t adBh = smem_u32(Bh) + (uint32_t)((la * BSTR + wn + lb * 8) * 2);

    float d[2][8][4];
#pragma unroll
    for (int i = 0; i < 2; i++)
#pragma unroll
        for (int j = 0; j < 8; j++)
#pragma unroll
            for (int q = 0; q < 4; q++) d[i][j][q] = 0.0f;

    // prologue: stages 0..STAGES-2
#pragma unroll
    for (int s = 0; s < STAGES - 1; s++) {
        cp_async16(adA + s * A_TILE * 2, aSrcBase + s * 16, aValid);
        cp_async16(adB + s * B_TILE * 2, bSrcBase + (size_t)(s * 16) * 256, 16);
        cp_commit();
    }

    for (int t = 0; t < 16; t++) {
        cp_wait<STAGES - 2>();
        __syncthreads();

        int nt = t + STAGES - 1;
        if (nt < 16) {
            int slot = nt & (STAGES - 1);
            cp_async16(adA + slot * A_TILE * 2, aSrcBase + nt * 16, aValid);
            cp_async16(adB + slot * B_TILE * 2, bSrcBase + (size_t)(nt * 16) * 256, 16);
        }
        cp_commit();

        int slot = t & (STAGES - 1);
        uint32_t aoff = (uint32_t)(slot * A_TILE * 2);
        uint32_t boff = (uint32_t)(slot * B_TILE * 2);
        uint32_t ah0[4], ah1[4];
        ldsm4(ah0, adAh + aoff);
        ldsm4(ah1, adAh + aoff + 16 * AS * 2);
#pragma unroll
        for (int q = 0; q < 4; q++) {
            uint32_t bh[4];
            ldsm4t(bh, adBh + boff + q * 32);
            mma_bf16(d[0][2 * q],     ah0, bh[0], bh[1]);
            mma_bf16(d[1][2 * q],     ah1, bh[0], bh[1]);
            mma_bf16(d[0][2 * q + 1], ah0, bh[2], bh[3]);
            mma_bf16(d[1][2 * q + 1], ah1, bh[2], bh[3]);
        }
    }

    // epilogue: * dis[row], convert to e4m3 pairs, 2B stores
#pragma unroll
    for (int ma = 0; ma < 2; ma++) {
        int r0 = bm + wm + 16 * ma + qr;
        int r1 = r0 + 8;
        float w0 = (r0 < M) ? g_dis[r0] : 0.0f;
        float w1 = (r1 < M) ? g_dis[r1] : 0.0f;
#pragma unroll
        for (int na = 0; na < 8; na++) {
            int c = bn + wn + 8 * na + 2 * qc;
            if (r0 < M) {
                uint16_t p = f2e4m3x2(d[ma][na][0] * w0, d[ma][na][1] * w0);
                *(uint16_t*)(&g_h8[(size_t)r0 * 256 + c]) = p;
            }
            if (r1 < M) {
                uint16_t p = f2e4m3x2(d[ma][na][2] * w1, d[ma][na][3] * w1);
                *(uint16_t*)(&g_h8[(size_t)r1 * 256 + c]) = p;
            }
        }
    }

    // ---- tail: scatter this block's slice of edges into CSR (+ coef) ----
    {
        int nblocks = gridDim.x * gridDim.y;
        int bid = blockIdx.y * gridDim.x + blockIdx.x;
        int per = (E + nblocks - 1) / nblocks;
        int e0 = bid * per;
        int e1 = min(e0 + per, E);
        for (int i = e0 + tid; i < e1; i += 256) {
            int s = esrc[i];
            int dd = edst[i];
            int p = atomicAdd(&g_cursor[dd], 1);
            g_col[p] = s;
            atomicAdd(&g_coef[s], g_dis[dd]);
        }
    }
}

// -------------------- fused aggregation + weighted reduce -------------------
// 8 rows / block (one warp per row). Lane l owns cols l*8..l*8+7 = one uint2
// of 8 e4m3; unpack cvt.rn.f16x2.e4m3x2, accumulate half2.

__device__ __forceinline__ __half2 e8_to_h2(uint16_t w) {
    uint32_t r;
    asm("cvt.rn.f16x2.e4m3x2 %0, %1;" : "=r"(r) : "h"(w));
    return *(__half2*)&r;
}

__global__ __launch_bounds__(256)
void k_agg_fused(const float* __restrict__ bias, int n) {
    __shared__ float sh[8][256];

    int lane = threadIdx.x & 31;
    int w = threadIdx.x >> 5;
    int i = blockIdx.x * 8 + w;

    const uint2* __restrict__ hp = (const uint2*)g_h8;  // row = 32 uint2
    float res[8];
#pragma unroll
    for (int q = 0; q < 8; q++) res[q] = 0.0f;

    if (i < n) {
        int s = g_rowptr[i];
        int t = g_rowptr[i + 1];
        float di = g_dis[i];
        float ci = di * (g_coef[i] + di);

        __half2 acc[4];
        {
            uint2 sv = hp[(size_t)i * 32 + lane];
            acc[0] = e8_to_h2((uint16_t)(sv.x & 0xffffu));
            acc[1] = e8_to_h2((uint16_t)(sv.x >> 16));
            acc[2] = e8_to_h2((uint16_t)(sv.y & 0xffffu));
            acc[3] = e8_to_h2((uint16_t)(sv.y >> 16));
        }

        for (int base = s; base < t; base += 32) {
            int m = min(32, t - base);
            int jv = (base + lane < t) ? g_col[base + lane] : 0;
#pragma unroll 8
            for (int k = 0; k < m; k++) {
                int j = __shfl_sync(0xffffffffu, jv, k);
                uint2 v = hp[(size_t)j * 32 + lane];
                acc[0] = __hadd2(acc[0], e8_to_h2((uint16_t)(v.x & 0xffffu)));
                acc[1] = __hadd2(acc[1], e8_to_h2((uint16_t)(v.x >> 16)));
                acc[2] = __hadd2(acc[2], e8_to_h2((uint16_t)(v.y & 0xffffu)));
                acc[3] = __hadd2(acc[3], e8_to_h2((uint16_t)(v.y >> 16)));
            }
        }

        float4 b0 = *(const float4*)(bias + lane * 8);
        float4 b1 = *(const float4*)(bias + lane * 8 + 4);
        float2 f0 = __half22float2(acc[0]);
        float2 f1 = __half22float2(acc[1]);
        float2 f2 = __half22float2(acc[2]);
        float2 f3 = __half22float2(acc[3]);
        res[0] = fmaxf(f0.x * di + b0.x, 0.f) * ci;
        res[1] = fmaxf(f0.y * di + b0.y, 0.f) * ci;
        res[2] = fmaxf(f1.x * di + b0.z, 0.f) * ci;
        res[3] = fmaxf(f1.y * di + b0.w, 0.f) * ci;
        res[4] = fmaxf(f2.x * di + b1.x, 0.f) * ci;
        res[5] = fmaxf(f2.y * di + b1.y, 0.f) * ci;
        res[6] = fmaxf(f3.x * di + b1.z, 0.f) * ci;
        res[7] = fmaxf(f3.y * di + b1.w, 0.f) * ci;
    }

#pragma unroll
    for (int q = 0; q < 8; q++) sh[w][lane * 8 + q] = res[q];
    __syncthreads();

    int c = threadIdx.x;
    float ssum = 0.0f;
#pragma unroll
    for (int q = 0; q < 8; q++) ssum += sh[q][c];
    g_part[(size_t)blockIdx.x * 256 + c] = ssum;
}

// ------------------------------- reductions --------------------------------

__global__ void k_reduce_stage1(int nb) {
    int c = threadIdx.x;
    int rows_per = (nb + 255) / 256;
    int r0 = blockIdx.x * rows_per;
    int r1 = min(r0 + rows_per, nb);
    float s = 0.0f;
    for (int r = r0; r < r1; r++) s += g_part[(size_t)r * 256 + c];
    g_part2[blockIdx.x * 256 + c] = s;
}

__global__ void k_final(const float* __restrict__ W2, const float* __restrict__ b2,
                        float* __restrict__ out, int n) {
    __shared__ float z[256];
    int c = threadIdx.x;
    float s = 0.0f;
    for (int b = 0; b < 256; b++) s += g_part2[b * 256 + c];
    z[c] = s / (float)n;
    __syncthreads();

    float o = b2[c];
#pragma unroll 8
    for (int k = 0; k < 256; k++) o += z[k] * W2[k * 256 + c];
    out[c] = o;
}

// -------------------------------- launch -----------------------------------

extern "C" void kernel_launch(void* const* d_in, const int* in_sizes, int n_in,
                              void* d_out, int out_size) {
    const float* x  = (const float*)d_in[0];
    const float* W1 = (const float*)d_in[1];
    const float* b1 = (const float*)d_in[2];
    const float* W2 = (const float*)d_in[3];
    const float* b2 = (const float*)d_in[4];
    const int*   ei = (const int*)d_in[5];

    int n = in_sizes[0] / DIM;
    int e = in_sizes[5] / 2;
    const int* src = ei;
    const int* dst = ei + e;
    float* out = (float*)d_out;

    int nb1024 = (n + 1023) / 1024;
    int agg_blocks = (n + 7) / 8;

    // zero deg/coef via memset nodes (not kernel launches)
    void* p_deg;
    void* p_coef;
    cudaGetSymbolAddress(&p_deg, g_deg);
    cudaGetSymbolAddress(&p_coef, g_coef);
    cudaMemsetAsync(p_deg, 0, (size_t)n * sizeof(int));
    cudaMemsetAsync(p_coef, 0, (size_t)n * sizeof(float));

    // --- degree count + bf16 conversion of x, W1 ---
    k_count_convert<<<(e + 255) / 256, 256>>>(dst, e, x, W1, n);
    k_block_sums<<<nb1024, 256>>>(n);          // dis + block totals
    k_scan_blocks<<<nb1024, 1024>>>(n, e);     // rowptr + cursor

    // --- layer-1 GEMM (bf16, cp.async x4 stages) + fused edge scatter ---
    dim3 gemm_grid(2, (n + 127) / 128);
    k_gemm_scatter<<<gemm_grid, 256>>>(n, src, dst, e);

    // --- fused aggregate + relu + weighted reduce (layer 2 collapsed) ---
    k_agg_fused<<<agg_blocks, 256>>>(b1, n);

    // --- reduce partials, matvec with W2, bias, mean ---
    k_reduce_stage1<<<256, 256>>>(agg_blocks);
    k_final<<<1, 256>>>(W2, b2, out, n);
}